// round 6
// baseline (speedup 1.0000x reference)
#include <cuda_runtime.h>
#include <cuda_fp16.h>
#include <stdint.h>

#define BATCH 16
#define SEQ 256
#define DIM 256
#define MAT 65536
#define NTOT 1048576
#define ABAR 0.042323627f   // 1/(1+sqrt(512))

// ---------------------------------------------------------------------------
// Device-global scratch
// ---------------------------------------------------------------------------
__device__ float g_x1att[NTOT];
__device__ float g_x2att[NTOT];
__device__ float g_n1[BATCH*SEQ];
__device__ float g_n2[BATCH*SEQ];
__device__ float g_sum[4];     // 0=x1, 1=x1_att, 2=x2, 3=x2_att
__device__ float g_sumsq[4];
__device__ float g_corr[DIM];  // ABAR*rowsum(W)+bias
__device__ __half g_x1h[NTOT];
__device__ __half g_x2h[NTOT];
__device__ __half g_Wh[SEQ*DIM];
__device__ __half g_d[NTOT];    // delta attn [b][j][i]
__device__ __half g_dT[NTOT];   // delta attn [b][i][j]

// ---------------------------------------------------------------------------
// Portable-ISA helpers (sm_80+)
// ---------------------------------------------------------------------------
__device__ __forceinline__ uint32_t smem_to_u32(const void* p) {
    uint32_t a;
    asm("{ .reg .u64 t; cvta.to.shared.u64 t, %1; cvt.u32.u64 %0, t; }" : "=r"(a) : "l"(p));
    return a;
}
__device__ __forceinline__ void ldsm4(uint32_t* r, uint32_t addr) {
    asm volatile("ldmatrix.sync.aligned.m8n8.x4.shared.b16 {%0,%1,%2,%3}, [%4];"
                 : "=r"(r[0]), "=r"(r[1]), "=r"(r[2]), "=r"(r[3]) : "r"(addr));
}
__device__ __forceinline__ void mma_fp16(float* c, const uint32_t* a, const uint32_t* b) {
    asm volatile("mma.sync.aligned.m16n8k16.row.col.f32.f16.f16.f32 "
                 "{%0,%1,%2,%3}, {%4,%5,%6,%7}, {%8,%9}, {%0,%1,%2,%3};"
                 : "+f"(c[0]), "+f"(c[1]), "+f"(c[2]), "+f"(c[3])
                 : "r"(a[0]), "r"(a[1]), "r"(a[2]), "r"(a[3]), "r"(b[0]), "r"(b[1]));
}
__device__ __forceinline__ void cp16(uint32_t saddr, const void* g) {
    asm volatile("cp.async.cg.shared.global [%0], [%1], 16;" :: "r"(saddr), "l"(g));
}
#define CP_COMMIT() asm volatile("cp.async.commit_group;" ::: "memory")
#define CP_WAIT0()  asm volatile("cp.async.wait_group 0;" ::: "memory")

// Full-K SMEM tile: 64 rows x 256 halfs, row padded to 528B (33x16B).
// Row stride 528B => ldsm 8-row fetch covers all 32 banks exactly once.
#define TROWF 528
#define TFULL (64 * TROWF)     // 33792 bytes

// ---------------------------------------------------------------------------
__global__ void k_zero() {
    int t = threadIdx.x;
    if (t < 4) { g_sum[t] = 0.f; g_sumsq[t] = 0.f; }
}

// ---------------------------------------------------------------------------
// k_prep: blocks [0,512) x1: norms+stats+fp16.  [512,1024) x2.
//         [1024,1088) W fp16 convert.  [1088,1120) corr = ABAR*rowsum(W)+bias
// ---------------------------------------------------------------------------
__global__ void __launch_bounds__(256) k_prep(const float* __restrict__ x1,
                                              const float* __restrict__ x2,
                                              const float* __restrict__ W,
                                              const float* __restrict__ bias) {
    int blk = blockIdx.x;
    int t = threadIdx.x;
    if (blk >= 1088) {   // corr rows
        int warp = t >> 5, lane = t & 31;
        int o = (blk - 1088) * 8 + warp;
        float s = 0.f;
#pragma unroll
        for (int c = 0; c < 8; c++) s += W[o * SEQ + lane + c * 32];
#pragma unroll
        for (int off = 16; off; off >>= 1) s += __shfl_xor_sync(0xffffffffu, s, off);
        if (lane == 0) g_corr[o] = ABAR * s + bias[o];
        return;
    }
    if (blk >= 1024) {   // W fp16
        int base = (blk - 1024) * 1024;
#pragma unroll
        for (int c = 0; c < 4; c++) {
            int i = base + c * 256 + t;
            g_Wh[i] = __float2half(W[i]);
        }
        return;
    }
    const float* X;
    float* Nrm;
    __half* Xh;
    int ch;
    if (blk < 512) { X = x1; Nrm = g_n1; Xh = g_x1h; ch = 0; }
    else           { X = x2; Nrm = g_n2; Xh = g_x2h; blk -= 512; ch = 2; }
    int warp = t >> 5, lane = t & 31;
    int row = blk * 8 + warp;
    const float* p = X + row * DIM;
    __half* ph = Xh + row * DIM;
    float s = 0.f, q = 0.f;
#pragma unroll
    for (int c = 0; c < 8; c++) {
        float v = p[lane + c * 32];
        s += v; q += v * v;
        ph[lane + c * 32] = __float2half(v);
    }
#pragma unroll
    for (int off = 16; off; off >>= 1) {
        s += __shfl_xor_sync(0xffffffffu, s, off);
        q += __shfl_xor_sync(0xffffffffu, q, off);
    }
    __shared__ float bs[8], bq[8];
    if (lane == 0) { Nrm[row] = q; bs[warp] = s; bq[warp] = q; }
    __syncthreads();
    if (t == 0) {
        float S = 0.f, Q = 0.f;
#pragma unroll
        for (int w = 0; w < 8; w++) { S += bs[w]; Q += bq[w]; }
        atomicAdd(&g_sum[ch], S);
        atomicAdd(&g_sumsq[ch], Q);
    }
}

// ---------------------------------------------------------------------------
// k_gemm1: fp16 HMMA  D[i][j] = x1_i . x2_j  (64x64 tile, full K=256 in SMEM)
// one cp.async wait + one barrier, then 16 barrier-free kk steps.
// epilogue: delta = 1/(sqrt(max(n1+n2-2D,0)+1e-6)+1) - ABAR -> g_dT, g_d.
// grid (4,4,16), 128 threads, 4 warps (2x2), warp tile 32x32.
// SMEM: [0,256) sn1 [256,512) sn2, A@1024 (TFULL), B@1024+TFULL
//       epilogue: th ushort[64][72] @1024 (tiles dead by then)
// ---------------------------------------------------------------------------
#define G_SMEM (1024 + 2 * TFULL)   // 68608

__global__ void __launch_bounds__(128) k_gemm1() {
    extern __shared__ char smem[];
    uint32_t sb = smem_to_u32(smem);
    float* sn1 = (float*)smem;
    float* sn2 = (float*)(smem + 256);
    int t = threadIdx.x, lane = t & 31, wid = t >> 5;
    int b = blockIdx.z, i0 = blockIdx.x * 64, j0 = blockIdx.y * 64;
    int m0w = (wid & 1) * 32, n0w = (wid >> 1) * 32;

    const __half* A = g_x1h + b * MAT + i0 * DIM;
    const __half* B = g_x2h + b * MAT + j0 * DIM;
    if (t < 64)  sn1[t]      = g_n1[b * SEQ + i0 + t];
    else         sn2[t - 64] = g_n2[b * SEQ + j0 + (t - 64)];

    const uint32_t sA = sb + 1024;
    const uint32_t sB = sA + TFULL;

    // load full K for both operands: 2048 cp16 each
#pragma unroll
    for (int s = 0; s < 16; s++) {
        int seg = t + s * 128;
        int row = seg >> 5, c = seg & 31;
        uint32_t so = (uint32_t)(row * TROWF + c * 16);
        cp16(sA + so, A + row * DIM + c * 8);
        cp16(sB + so, B + row * DIM + c * 8);
    }
    CP_COMMIT();
    CP_WAIT0();
    __syncthreads();

    float acc[2][4][4] = {};
#pragma unroll
    for (int kk = 0; kk < 16; kk++) {
        uint32_t af[2][4];
#pragma unroll
        for (int mi = 0; mi < 2; mi++)
            ldsm4(af[mi], sA + (uint32_t)((m0w + mi * 16 + (lane & 15)) * TROWF
                                          + kk * 32 + (lane >> 4) * 16));
        uint32_t bf[4][2];
#pragma unroll
        for (int np = 0; np < 2; np++) {
            uint32_t r[4];
            ldsm4(r, sB + (uint32_t)((n0w + np * 16 + (lane & 7) + ((lane >> 4) & 1) * 8) * TROWF
                                      + kk * 32 + ((lane >> 3) & 1) * 16));
            bf[np * 2][0] = r[0]; bf[np * 2][1] = r[1];
            bf[np * 2 + 1][0] = r[2]; bf[np * 2 + 1][1] = r[3];
        }
#pragma unroll
        for (int mi = 0; mi < 2; mi++)
#pragma unroll
            for (int ni = 0; ni < 4; ni++)
                mma_fp16(acc[mi][ni], af[mi], bf[ni]);
    }
    __syncthreads();   // tiles dead; th overlays sA

    // epilogue: delta fp16 into SMEM tile [64][72]
    unsigned short* th = (unsigned short*)(smem + 1024);
#pragma unroll
    for (int mi = 0; mi < 2; mi++) {
#pragma unroll
        for (int ni = 0; ni < 4; ni++) {
#pragma unroll
            for (int h = 0; h < 2; h++) {
                int row = m0w + mi * 16 + (lane >> 2) + h * 8;
                int col = n0w + ni * 8 + (lane & 3) * 2;
                float n1v = sn1[row];
                float e0 = fmaxf(n1v + sn2[col]     - 2.f * acc[mi][ni][h * 2],     0.f);
                float e1 = fmaxf(n1v + sn2[col + 1] - 2.f * acc[mi][ni][h * 2 + 1], 0.f);
                float a0 = 1.f / (sqrtf(e0 + 1e-6f) + 1.f) - ABAR;
                float a1 = 1.f / (sqrtf(e1 + 1e-6f) + 1.f) - ABAR;
                __half2 pk = __floats2half2_rn(a0, a1);
                *(__half2*)&th[row * 72 + col] = pk;
            }
        }
    }
    __syncthreads();
    // g_dT [b][i][j]: contiguous rows
    {
        int i = t >> 1, qh = (t & 1) * 32;
        int gT = b * MAT + (i0 + i) * SEQ + j0 + qh;
#pragma unroll
        for (int p = 0; p < 4; p++)
            *(uint4*)&g_dT[gT + p * 8] = *(uint4*)&th[i * 72 + qh + p * 8];
    }
    // g_d [b][j][i]: transpose gather
    {
        int j = t >> 1, ih = (t & 1) * 32;
        int g = b * MAT + (j0 + j) * SEQ + i0 + ih;
#pragma unroll
        for (int p = 0; p < 4; p++) {
            uint32_t w[4];
#pragma unroll
            for (int pp = 0; pp < 4; pp++) {
                int r0 = ih + p * 8 + pp * 2;
                w[pp] = (uint32_t)th[r0 * 72 + j] | ((uint32_t)th[(r0 + 1) * 72 + j] << 16);
            }
            *(uint4*)&g_d[g + p * 8] = make_uint4(w[0], w[1], w[2], w[3]);
        }
    }
}

// ---------------------------------------------------------------------------
// k_gemm2: fp16 HMMA  out = delta(.T) @ W^T + corr  (64x64 tile, full K=256)
// grid (4,4,32): x->o-tile, y->r-tile, z=b*2+which (0: x2_att ch3, 1: x1_att ch1)
// 128 threads, 4 warps (2x2), warp tile 32x32. Barrier-free compute.
// ---------------------------------------------------------------------------
__global__ void __launch_bounds__(128) k_gemm2() {
    extern __shared__ char smem[];
    uint32_t sb = smem_to_u32(smem);
    float* scorr = (float*)smem;
    int t = threadIdx.x, lane = t & 31, wid = t >> 5;
    int bz = blockIdx.z, b = bz >> 1, which = bz & 1;
    int o0 = blockIdx.x * 64, r0 = blockIdx.y * 64;
    int m0w = (wid & 1) * 32, n0w = (wid >> 1) * 32;

    const __half* A = (which ? g_dT : g_d) + b * MAT + r0 * SEQ;
    const __half* Wp = g_Wh + o0 * SEQ;
    if (t < 64) scorr[t] = g_corr[o0 + t];

    const uint32_t sA = sb + 1024;
    const uint32_t sW = sA + TFULL;

#pragma unroll
    for (int s = 0; s < 16; s++) {
        int seg = t + s * 128;
        int row = seg >> 5, c = seg & 31;
        uint32_t so = (uint32_t)(row * TROWF + c * 16);
        cp16(sA + so, A + row * SEQ + c * 8);
        cp16(sW + so, Wp + row * SEQ + c * 8);
    }
    CP_COMMIT();
    CP_WAIT0();
    __syncthreads();

    float acc[2][4][4] = {};
#pragma unroll
    for (int kk = 0; kk < 16; kk++) {
        uint32_t bf[4][2];
#pragma unroll
        for (int np = 0; np < 2; np++) {
            uint32_t r[4];
            ldsm4(r, sW + (uint32_t)((n0w + np * 16 + (lane & 7) + ((lane >> 4) & 1) * 8) * TROWF
                                      + kk * 32 + ((lane >> 3) & 1) * 16));
            bf[np * 2][0] = r[0]; bf[np * 2][1] = r[1];
            bf[np * 2 + 1][0] = r[2]; bf[np * 2 + 1][1] = r[3];
        }
#pragma unroll
        for (int mi = 0; mi < 2; mi++) {
            uint32_t af[4];
            ldsm4(af, sA + (uint32_t)((m0w + mi * 16 + (lane & 15)) * TROWF
                                       + kk * 32 + (lane >> 4) * 16));
#pragma unroll
            for (int ni = 0; ni < 4; ni++)
                mma_fp16(acc[mi][ni], af, bf[ni]);
        }
    }

    // epilogue: +corr, fp32 store, BN stats
    float* out = which ? g_x1att : g_x2att;
    float ps = 0.f, pq = 0.f;
#pragma unroll
    for (int mi = 0; mi < 2; mi++) {
#pragma unroll
        for (int ni = 0; ni < 4; ni++) {
#pragma unroll
            for (int h = 0; h < 2; h++) {
                int row = r0 + m0w + mi * 16 + (lane >> 2) + h * 8;
                int colL = n0w + ni * 8 + (lane & 3) * 2;
                float v0 = acc[mi][ni][h * 2]     + scorr[colL];
                float v1 = acc[mi][ni][h * 2 + 1] + scorr[colL + 1];
                *(float2*)&out[b * MAT + row * DIM + o0 + colL] = make_float2(v0, v1);
                ps += v0 + v1;
                pq += v0 * v0 + v1 * v1;
            }
        }
    }
#pragma unroll
    for (int off = 16; off; off >>= 1) {
        ps += __shfl_xor_sync(0xffffffffu, ps, off);
        pq += __shfl_xor_sync(0xffffffffu, pq, off);
    }
    float* ws = (float*)(smem + 256);
    float* wq = ws + 4;
    __syncthreads();
    if (lane == 0) { ws[wid] = ps; wq[wid] = pq; }
    __syncthreads();
    if (t == 0) {
        float S = ws[0] + ws[1] + ws[2] + ws[3];
        float Q = wq[0] + wq[1] + wq[2] + wq[3];
        int ch = which ? 1 : 3;
        atomicAdd(&g_sum[ch], S);
        atomicAdd(&g_sumsq[ch], Q);
    }
}

// ---------------------------------------------------------------------------
// k_bn: apply training-mode BN, write both outputs
// out layout: [which_out(2)][b(16)][c(2)][s(256)][d(256)]
// ---------------------------------------------------------------------------
__global__ void __launch_bounds__(256) k_bn(const float* __restrict__ x1,
                                            const float* __restrict__ x2,
                                            const float* __restrict__ gamma,
                                            const float* __restrict__ beta,
                                            float* __restrict__ out) {
    int idx = blockIdx.x * blockDim.x + threadIdx.x;
    int e = idx << 2;
    int which = e >> 21;
    int rem = e & ((1 << 21) - 1);
    int bb = rem >> 17;
    int c = (rem >> 16) & 1;
    int pos = rem & 65535;
    const float* src;
    int ch;
    if (which == 0) { src = c ? g_x1att : x1; ch = c ? 1 : 0; }
    else            { src = c ? g_x2att : x2; ch = c ? 3 : 2; }
    const float Ninv = 1.0f / (float)NTOT;
    float mean = g_sum[ch] * Ninv;
    float var = g_sumsq[ch] * Ninv - mean * mean;
    float sc = gamma[c] * rsqrtf(var + 1e-5f);
    float sh = beta[c] - mean * sc;
    float4 v = *(const float4*)&src[bb * MAT + pos];
    float4 o;
    o.x = v.x * sc + sh;
    o.y = v.y * sc + sh;
    o.z = v.z * sc + sh;
    o.w = v.w * sc + sh;
    *(float4*)&out[e] = o;
}

// ---------------------------------------------------------------------------
extern "C" void kernel_launch(void* const* d_in, const int* in_sizes, int n_in,
                              void* d_out, int out_size) {
    const float* x1    = (const float*)d_in[0];
    const float* x2    = (const float*)d_in[1];
    const float* W     = (const float*)d_in[2];
    const float* bias  = (const float*)d_in[3];
    const float* gamma = (const float*)d_in[4];
    const float* beta  = (const float*)d_in[5];
    float* out = (float*)d_out;

    cudaFuncSetAttribute(k_gemm1, cudaFuncAttributeMaxDynamicSharedMemorySize, G_SMEM);
    cudaFuncSetAttribute(k_gemm2, cudaFuncAttributeMaxDynamicSharedMemorySize, G_SMEM);

    k_zero<<<1, 32>>>();
    k_prep<<<1120, 256>>>(x1, x2, W, bias);
    k_gemm1<<<dim3(4, 4, 16), 128, G_SMEM>>>();
    k_gemm2<<<dim3(4, 4, 32), 128, G_SMEM>>>();
    k_bn<<<4096, 256>>>(x1, x2, gamma, beta, out);
}

// round 7
// speedup vs baseline: 1.1393x; 1.1393x over previous
#include <cuda_runtime.h>
#include <cuda_fp16.h>
#include <stdint.h>

#define BATCH 16
#define SEQ 256
#define DIM 256
#define MAT 65536
#define NTOT 1048576
#define ABAR 0.042323627f   // 1/(1+sqrt(512))

// ---------------------------------------------------------------------------
// Device-global scratch
// ---------------------------------------------------------------------------
__device__ float g_x1att[NTOT];
__device__ float g_x2att[NTOT];
__device__ float g_n1[BATCH*SEQ];
__device__ float g_n2[BATCH*SEQ];
__device__ float g_sum[4];     // 0=x1, 1=x1_att, 2=x2, 3=x2_att
__device__ float g_sumsq[4];
__device__ float g_corr[DIM];  // ABAR*rowsum(W)+bias
__device__ __half g_x1h[NTOT];
__device__ __half g_x2h[NTOT];
__device__ __half g_Wh[SEQ*DIM];

// ---------------------------------------------------------------------------
// Portable-ISA helpers (sm_80+)
// ---------------------------------------------------------------------------
__device__ __forceinline__ uint32_t smem_to_u32(const void* p) {
    uint32_t a;
    asm("{ .reg .u64 t; cvta.to.shared.u64 t, %1; cvt.u32.u64 %0, t; }" : "=r"(a) : "l"(p));
    return a;
}
__device__ __forceinline__ void ldsm4(uint32_t* r, uint32_t addr) {
    asm volatile("ldmatrix.sync.aligned.m8n8.x4.shared.b16 {%0,%1,%2,%3}, [%4];"
                 : "=r"(r[0]), "=r"(r[1]), "=r"(r[2]), "=r"(r[3]) : "r"(addr));
}
__device__ __forceinline__ void mma_fp16(float* c, const uint32_t* a, const uint32_t* b) {
    asm volatile("mma.sync.aligned.m16n8k16.row.col.f32.f16.f16.f32 "
                 "{%0,%1,%2,%3}, {%4,%5,%6,%7}, {%8,%9}, {%0,%1,%2,%3};"
                 : "+f"(c[0]), "+f"(c[1]), "+f"(c[2]), "+f"(c[3])
                 : "r"(a[0]), "r"(a[1]), "r"(a[2]), "r"(a[3]), "r"(b[0]), "r"(b[1]));
}
__device__ __forceinline__ void cp16(uint32_t saddr, const void* g) {
    asm volatile("cp.async.cg.shared.global [%0], [%1], 16;" :: "r"(saddr), "l"(g));
}
#define CP_COMMIT() asm volatile("cp.async.commit_group;" ::: "memory")
#define CP_WAIT1()  asm volatile("cp.async.wait_group 1;" ::: "memory")
#define CP_WAIT0()  asm volatile("cp.async.wait_group 0;" ::: "memory")

// SMEM geometry for the fused kernel
#define PR 528                  // pitch of 256-half rows (33x16B, conflict-free)
#define PB 144                  // pitch of 64-half rows
#define BTILE (256 * PB)        // 36864 bytes: one B chunk [256 n][64 k]
#define OFF_SNC   0             // 256 floats
#define OFF_SNR   1024          // 32 floats
#define OFF_CORR  1152          // 256 floats
#define OFF_SR    2176          // 32 x PR = 16896
#define OFF_SAT   19072         // 32 x PR = 16896
#define OFF_SD    35968         // 2 x BTILE = 73728
#define OFF_STAT  109696        // 16 floats
#define F_SMEM    109760

// ---------------------------------------------------------------------------
__global__ void k_zero() {
    int t = threadIdx.x;
    if (t < 4) { g_sum[t] = 0.f; g_sumsq[t] = 0.f; }
}

// ---------------------------------------------------------------------------
// k_prep: blocks [0,512) x1: norms+stats+fp16.  [512,1024) x2.
//         [1024,1088) W fp16 convert.  [1088,1120) corr = ABAR*rowsum(W)+bias
// ---------------------------------------------------------------------------
__global__ void __launch_bounds__(256) k_prep(const float* __restrict__ x1,
                                              const float* __restrict__ x2,
                                              const float* __restrict__ W,
                                              const float* __restrict__ bias) {
    int blk = blockIdx.x;
    int t = threadIdx.x;
    if (blk >= 1088) {   // corr rows
        int warp = t >> 5, lane = t & 31;
        int o = (blk - 1088) * 8 + warp;
        float s = 0.f;
#pragma unroll
        for (int c = 0; c < 8; c++) s += W[o * SEQ + lane + c * 32];
#pragma unroll
        for (int off = 16; off; off >>= 1) s += __shfl_xor_sync(0xffffffffu, s, off);
        if (lane == 0) g_corr[o] = ABAR * s + bias[o];
        return;
    }
    if (blk >= 1024) {   // W fp16
        int base = (blk - 1024) * 1024;
#pragma unroll
        for (int c = 0; c < 4; c++) {
            int i = base + c * 256 + t;
            g_Wh[i] = __float2half(W[i]);
        }
        return;
    }
    const float* X;
    float* Nrm;
    __half* Xh;
    int ch;
    if (blk < 512) { X = x1; Nrm = g_n1; Xh = g_x1h; ch = 0; }
    else           { X = x2; Nrm = g_n2; Xh = g_x2h; blk -= 512; ch = 2; }
    int warp = t >> 5, lane = t & 31;
    int row = blk * 8 + warp;
    const float* p = X + row * DIM;
    __half* ph = Xh + row * DIM;
    float s = 0.f, q = 0.f;
#pragma unroll
    for (int c = 0; c < 8; c++) {
        float v = p[lane + c * 32];
        s += v; q += v * v;
        ph[lane + c * 32] = __float2half(v);
    }
#pragma unroll
    for (int off = 16; off; off >>= 1) {
        s += __shfl_xor_sync(0xffffffffu, s, off);
        q += __shfl_xor_sync(0xffffffffu, q, off);
    }
    __shared__ float bs[8], bq[8];
    if (lane == 0) { Nrm[row] = q; bs[warp] = s; bq[warp] = q; }
    __syncthreads();
    if (t == 0) {
        float S = 0.f, Q = 0.f;
#pragma unroll
        for (int w = 0; w < 8; w++) { S += bs[w]; Q += bq[w]; }
        atomicAdd(&g_sum[ch], S);
        atomicAdd(&g_sumsq[ch], Q);
    }
}

// ---------------------------------------------------------------------------
// k_att: FUSED attention + projection.
// grid (8, 32): x = j-block (32 rows), y = b*2+which.
//   which=0: rows from x2, cols from x1 -> x2_att rows (ch 3)
//   which=1: rows from x1, cols from x2 -> x1_att rows (ch 1)
// Stage 1: delta[r][i] = 1/(1+sqrt(max(nr+nc-2*R·C,0)+1e-6)) - ABAR
//          (M=32, N=256, K=256) -> SMEM strip [32][256] fp16
// Stage 2: out[r][o] = delta @ W^T + corr  (M=32, N=256, K=256)
// One continuous cp.async double-buffer pipeline covers Y chunks then W chunks.
// 256 threads, 8 warps: wm = wid&1 (m16), wn = wid>>1 (n64).
// ---------------------------------------------------------------------------
__global__ void __launch_bounds__(256, 2) k_att() {
    extern __shared__ char smem[];
    uint32_t sb = smem_to_u32(smem);
    float* snc   = (float*)(smem + OFF_SNC);
    float* snr   = (float*)(smem + OFF_SNR);
    float* scorr = (float*)(smem + OFF_CORR);
    int t = threadIdx.x, lane = t & 31, wid = t >> 5;
    int jb = blockIdx.x;
    int bz = blockIdx.y, b = bz >> 1, which = bz & 1;

    const __half* R = (which ? g_x1h : g_x2h) + b * MAT + jb * 32 * DIM;
    const __half* C = (which ? g_x2h : g_x1h) + b * MAT;
    const float* NR = (which ? g_n1 : g_n2) + b * SEQ + jb * 32;
    const float* NC = (which ? g_n2 : g_n1) + b * SEQ;
    float* out = (which ? g_x1att : g_x2att) + b * MAT + jb * 32 * DIM;
    int ch = which ? 1 : 3;

    snc[t] = NC[t];
    if (t < 32) snr[t] = NR[t];
    scorr[t] = g_corr[t];

    const uint32_t sR  = sb + OFF_SR;
    const uint32_t sAt = sb + OFF_SAT;
    const uint32_t sD  = sb + OFF_SD;

    // B-chunk loader: [256 n][64 k] from src (row pitch 256 halfs)
    auto loadB = [&](const __half* src, int kc, int buf) {
#pragma unroll
        for (int s = 0; s < 8; s++) {
            int seg = t + s * 256;
            int row = seg >> 3, c = seg & 7;
            cp16(sD + (uint32_t)(buf * BTILE + row * PB + c * 16),
                 src + row * SEQ + kc * 64 + c * 8);
        }
    };

    // R strip [32][256] + first Y chunk = group 0
#pragma unroll
    for (int s = 0; s < 4; s++) {
        int seg = t + s * 256;
        int row = seg >> 5, c = seg & 31;
        cp16(sR + (uint32_t)(row * PR + c * 16), R + row * DIM + c * 8);
    }
    loadB(C, 0, 0);
    CP_COMMIT();

    int m0 = (wid & 1) * 16, n0 = (wid >> 1) * 64;
    float acc[8][4] = {};

    // ---- stage 1: 4 K-chunks over dim ----
    for (int kc = 0; kc < 4; kc++) {
        if (kc < 3) loadB(C, kc + 1, (kc + 1) & 1);
        else        loadB(g_Wh, 0, 0);          // prefetch W chunk 0
        CP_COMMIT();
        CP_WAIT1();
        __syncthreads();
        uint32_t bufB = sD + (kc & 1) * BTILE;
#pragma unroll
        for (int kk = 0; kk < 4; kk++) {
            uint32_t af[4];
            ldsm4(af, sR + (uint32_t)((m0 + (lane & 15)) * PR
                                      + kc * 128 + kk * 32 + (lane >> 4) * 16));
            uint32_t bf[8][2];
#pragma unroll
            for (int np = 0; np < 4; np++) {
                uint32_t r[4];
                ldsm4(r, bufB + (uint32_t)((n0 + np * 16 + (lane & 7) + ((lane >> 4) & 1) * 8) * PB
                                            + kk * 32 + ((lane >> 3) & 1) * 16));
                bf[np * 2][0] = r[0]; bf[np * 2][1] = r[1];
                bf[np * 2 + 1][0] = r[2]; bf[np * 2 + 1][1] = r[3];
            }
#pragma unroll
            for (int ni = 0; ni < 8; ni++)
                mma_fp16(acc[ni], af, bf[ni]);
        }
        __syncthreads();
    }

    // ---- stage-1 epilogue: delta -> sAt, reset acc ----
#pragma unroll
    for (int ni = 0; ni < 8; ni++) {
#pragma unroll
        for (int h = 0; h < 2; h++) {
            int row = m0 + (lane >> 2) + h * 8;
            int col = n0 + ni * 8 + (lane & 3) * 2;
            float e0 = fmaxf(snr[row] + snc[col]     - 2.f * acc[ni][h * 2],     0.f);
            float e1 = fmaxf(snr[row] + snc[col + 1] - 2.f * acc[ni][h * 2 + 1], 0.f);
            float a0 = 1.f / (sqrtf(e0 + 1e-6f) + 1.f) - ABAR;
            float a1 = 1.f / (sqrtf(e1 + 1e-6f) + 1.f) - ABAR;
            *(__half2*)(smem + OFF_SAT + row * PR + col * 2) = __floats2half2_rn(a0, a1);
            acc[ni][h * 2] = 0.f;
            acc[ni][h * 2 + 1] = 0.f;
        }
    }
    __syncthreads();

    // ---- stage 2: 4 K-chunks over i (A = sAt, B = W chunks) ----
    for (int kc = 0; kc < 4; kc++) {
        if (kc < 3) loadB(g_Wh, kc + 1, (kc + 1) & 1);
        CP_COMMIT();
        if (kc < 3) CP_WAIT1(); else CP_WAIT0();
        __syncthreads();
        uint32_t bufB = sD + (kc & 1) * BTILE;
#pragma unroll
        for (int kk = 0; kk < 4; kk++) {
            uint32_t af[4];
            ldsm4(af, sAt + (uint32_t)((m0 + (lane & 15)) * PR
                                       + kc * 128 + kk * 32 + (lane >> 4) * 16));
            uint32_t bf[8][2];
#pragma unroll
            for (int np = 0; np < 4; np++) {
                uint32_t r[4];
                ldsm4(r, bufB + (uint32_t)((n0 + np * 16 + (lane & 7) + ((lane >> 4) & 1) * 8) * PB
                                            + kk * 32 + ((lane >> 3) & 1) * 16));
                bf[np * 2][0] = r[0]; bf[np * 2][1] = r[1];
                bf[np * 2 + 1][0] = r[2]; bf[np * 2 + 1][1] = r[3];
            }
#pragma unroll
            for (int ni = 0; ni < 8; ni++)
                mma_fp16(acc[ni], af, bf[ni]);
        }
        __syncthreads();
    }

    // ---- stage-2 epilogue: +corr, fp32 store, BN stats ----
    float ps = 0.f, pq = 0.f;
#pragma unroll
    for (int ni = 0; ni < 8; ni++) {
#pragma unroll
        for (int h = 0; h < 2; h++) {
            int row = m0 + (lane >> 2) + h * 8;
            int col = n0 + ni * 8 + (lane & 3) * 2;
            float v0 = acc[ni][h * 2]     + scorr[col];
            float v1 = acc[ni][h * 2 + 1] + scorr[col + 1];
            *(float2*)&out[row * DIM + col] = make_float2(v0, v1);
            ps += v0 + v1;
            pq += v0 * v0 + v1 * v1;
        }
    }
#pragma unroll
    for (int off = 16; off; off >>= 1) {
        ps += __shfl_xor_sync(0xffffffffu, ps, off);
        pq += __shfl_xor_sync(0xffffffffu, pq, off);
    }
    float* ws = (float*)(smem + OFF_STAT);
    float* wq = ws + 8;
    if (lane == 0) { ws[wid] = ps; wq[wid] = pq; }
    __syncthreads();
    if (t == 0) {
        float S = 0.f, Q = 0.f;
#pragma unroll
        for (int w = 0; w < 8; w++) { S += ws[w]; Q += wq[w]; }
        atomicAdd(&g_sum[ch], S);
        atomicAdd(&g_sumsq[ch], Q);
    }
}

// ---------------------------------------------------------------------------
// k_bn: apply training-mode BN, write both outputs
// out layout: [which_out(2)][b(16)][c(2)][s(256)][d(256)]
// ---------------------------------------------------------------------------
__global__ void __launch_bounds__(256) k_bn(const float* __restrict__ x1,
                                            const float* __restrict__ x2,
                                            const float* __restrict__ gamma,
                                            const float* __restrict__ beta,
                                            float* __restrict__ out) {
    int idx = blockIdx.x * blockDim.x + threadIdx.x;
    int e = idx << 2;
    int which = e >> 21;
    int rem = e & ((1 << 21) - 1);
    int bb = rem >> 17;
    int c = (rem >> 16) & 1;
    int pos = rem & 65535;
    const float* src;
    int ch;
    if (which == 0) { src = c ? g_x1att : x1; ch = c ? 1 : 0; }
    else            { src = c ? g_x2att : x2; ch = c ? 3 : 2; }
    const float Ninv = 1.0f / (float)NTOT;
    float mean = g_sum[ch] * Ninv;
    float var = g_sumsq[ch] * Ninv - mean * mean;
    float sc = gamma[c] * rsqrtf(var + 1e-5f);
    float sh = beta[c] - mean * sc;
    float4 v = *(const float4*)&src[bb * MAT + pos];
    float4 o;
    o.x = v.x * sc + sh;
    o.y = v.y * sc + sh;
    o.z = v.z * sc + sh;
    o.w = v.w * sc + sh;
    *(float4*)&out[e] = o;
}

// ---------------------------------------------------------------------------
extern "C" void kernel_launch(void* const* d_in, const int* in_sizes, int n_in,
                              void* d_out, int out_size) {
    const float* x1    = (const float*)d_in[0];
    const float* x2    = (const float*)d_in[1];
    const float* W     = (const float*)d_in[2];
    const float* bias  = (const float*)d_in[3];
    const float* gamma = (const float*)d_in[4];
    const float* beta  = (const float*)d_in[5];
    float* out = (float*)d_out;

    cudaFuncSetAttribute(k_att, cudaFuncAttributeMaxDynamicSharedMemorySize, F_SMEM);

    k_zero<<<1, 32>>>();
    k_prep<<<1120, 256>>>(x1, x2, W, bias);
    k_att<<<dim3(8, 32), 256, F_SMEM>>>();
    k_bn<<<4096, 256>>>(x1, x2, gamma, beta, out);
}